// round 9
// baseline (speedup 1.0000x reference)
#include <cuda_runtime.h>

#define H 1024
#define T 20
#define GRID 128
#define BLK 512

// Dynamic smem layout (floats). Total 22008 floats = 88032 B (< 227 KB cap).
#define OFF_D0   0          // [T][H] dec0 outputs (80 KB)
#define OFF_VEC  20480      // [H] staged h0 vector
#define OFF_PART 21504      // [16] per-warp partials
#define OFF_H1   21520      // [8] this block's h1 channels
#define OFF_PRE  21528      // [2][8][T] dec1 pre-activation K-half partials
#define OFF_D1   21848      // [8][T] dec1 outputs
#define SMEM_FLOATS 22008

// Scratch (__device__ globals per alloc-free rule).
// g_pre: parity-double-buffered accumulator. Buffer (g_gen&1) accumulates this
// launch (starts zero: zero-init at load, then re-zeroed by the PREVIOUS launch);
// each block zeroes its 8 channels of the other buffer for the NEXT launch.
__device__ float g_pre[2][H] = {};
__device__ unsigned g_cnt = 0;   // barrier arrival counter (self-resets)
__device__ unsigned g_gen = 0;   // barrier generation (monotonic, +1 per launch)

__device__ __forceinline__ float warp_reduce(float v) {
#pragma unroll
    for (int o = 16; o; o >>= 1) v += __shfl_xor_sync(0xffffffffu, v, o);
    return v;
}

// Sense-reversal grid barrier. GRID=128 <= 148 SMs at 1 block/SM -> all blocks
// co-resident in one wave, spin is deadlock-free. Counter self-resets each use.
__device__ __forceinline__ void grid_barrier() {
    __syncthreads();
    if (threadIdx.x == 0) {
        __threadfence();                                  // release our writes/atomics
        unsigned gen = *(volatile unsigned*)&g_gen;
        if (atomicAdd(&g_cnt, 1u) == GRID - 1) {
            g_cnt = 0;
            __threadfence();
            atomicAdd(&g_gen, 1u);
        } else {
            while (*(volatile unsigned*)&g_gen == gen) {}
        }
        __threadfence();                                  // acquire others' writes
    }
    __syncthreads();
}

__global__ void __launch_bounds__(BLK, 1) fused_net(
    const float* __restrict__ x,
    const float* __restrict__ enc_w0, const float* __restrict__ enc_b0,
    const float* __restrict__ enc_w1, const float* __restrict__ enc_b1,
    const float* __restrict__ dec_w0, const float* __restrict__ dec_u0,
    const float* __restrict__ dec_b0,
    const float* __restrict__ dec_w1, const float* __restrict__ dec_u1,
    const float* __restrict__ dec_b1,
    const float* __restrict__ out_w, const float* __restrict__ out_b,
    float* __restrict__ out)
{
    extern __shared__ float smem[];
    const int tid = threadIdx.x;
    const int warp = tid >> 5, lane = tid & 31;
    const int row = warp & 7;          // phase 1: row index in block
    const int half = warp >> 3;        // phase 1: K-half
    const int h = blockIdx.x * 8 + row;

    // Accumulation-buffer parity: g_gen changes only at the barrier (after ALL
    // blocks arrive), so every block reads the same value here.
    const unsigned p = (*(volatile unsigned*)&g_gen) & 1u;
    if (tid < 8) g_pre[1u ^ p][blockIdx.x * 8 + tid] = 0.0f;   // for NEXT launch

    // ---- Entry loads, critical first: enc_w1 half-row, enc_w0 -> s_vec.
    float4 wa, wb, wc, wd;
    {
        const float4* w1p = (const float4*)(enc_w1 + (size_t)h * H) + half * 128;
        wa = __ldg(w1p + lane);
        wb = __ldg(w1p + 32 + lane);
        wc = __ldg(w1p + 64 + lane);
        wd = __ldg(w1p + 96 + lane);
    }
    // x: (20, 4096, 2); x[0, 4095, :] at flat {8190, 8191}. h_{-1}=0 => enc_u unused.
    const float x0 = x[8190], x1 = x[8191];
    float* s_vec = smem + OFF_VEC;
#pragma unroll
    for (int i = tid; i < H; i += BLK) {
        float v = fmaf(enc_w0[2 * i], x0, fmaf(enc_w0[2 * i + 1], x1, enc_b0[i]));
        s_vec[i] = fmaxf(v, 0.0f);
    }
    // dec_w0 column slice for this thread's 2 output channels (divergent but
    // only 32 KB/block; overlaps everything below).
    const int g0 = 2 * tid;            // channels g0, g0+1
    float4 ca0, ca1, cb0, cb1;
    {
        const float4* c0 = (const float4*)(dec_w0 + (size_t)g0 * H + blockIdx.x * 8);
        const float4* c1 = (const float4*)(dec_w0 + (size_t)(g0 + 1) * H + blockIdx.x * 8);
        ca0 = __ldg(c0); ca1 = __ldg(c0 + 1);
        cb0 = __ldg(c1); cb1 = __ldg(c1 + 1);
    }
    // Phase-3 dec_w1 slice (2 rows x 512 K per warp), issued last: consumed
    // only after the barrier, so its DRAM latency drains under segment A.
    const int rp = warp & 3;             // row pair: rows [rp*2, +2)
    const int kh = (warp >> 2) & 1;      // K-half
    const int th = warp >> 3;            // t-half
    const int h0 = blockIdx.x * 8 + rp * 2;
    float4 w8[8];
    {
        const float4* wb4 = (const float4*)dec_w1 + ((size_t)h0 * H + kh * 512) / 4;
#pragma unroll
        for (int r = 0; r < 2; r++)
#pragma unroll
            for (int j = 0; j < 4; j++)
                w8[r * 4 + j] = __ldg(wb4 + r * 256 + j * 32 + lane);
    }

    // ---- Segment A: h1 = relu(enc_w1 @ relu(enc_w0 @ x + b0) + b1) for this
    //      block's 8 channels, then column-parallel dec_w0 partials -> g_pre.
    {
        __syncthreads();
        const float4* s4 = (const float4*)s_vec + half * 128;
        float4 v0 = s4[lane], v1 = s4[32 + lane], v2 = s4[64 + lane], v3 = s4[96 + lane];
        float acc = 0.0f;
        acc = fmaf(wa.x, v0.x, acc); acc = fmaf(wa.y, v0.y, acc);
        acc = fmaf(wa.z, v0.z, acc); acc = fmaf(wa.w, v0.w, acc);
        acc = fmaf(wb.x, v1.x, acc); acc = fmaf(wb.y, v1.y, acc);
        acc = fmaf(wb.z, v1.z, acc); acc = fmaf(wb.w, v1.w, acc);
        acc = fmaf(wc.x, v2.x, acc); acc = fmaf(wc.y, v2.y, acc);
        acc = fmaf(wc.z, v2.z, acc); acc = fmaf(wc.w, v2.w, acc);
        acc = fmaf(wd.x, v3.x, acc); acc = fmaf(wd.y, v3.y, acc);
        acc = fmaf(wd.z, v3.z, acc); acc = fmaf(wd.w, v3.w, acc);
        acc = warp_reduce(acc);
        if (lane == 0) smem[OFF_PART + warp] = acc;
        __syncthreads();
        if (tid < 8)
            smem[OFF_H1 + tid] = fmaxf(smem[OFF_PART + tid] + smem[OFF_PART + tid + 8]
                                       + enc_b1[blockIdx.x * 8 + tid], 0.0f);
        __syncthreads();

        // Partial pre0 contributions for channels g0, g0+1 (16 FMAs) + scatter.
        const float h1v[8] = { smem[OFF_H1+0], smem[OFF_H1+1], smem[OFF_H1+2],
                               smem[OFF_H1+3], smem[OFF_H1+4], smem[OFF_H1+5],
                               smem[OFF_H1+6], smem[OFF_H1+7] };
        float pa = 0.0f, pb = 0.0f;
        pa = fmaf(ca0.x, h1v[0], pa); pa = fmaf(ca0.y, h1v[1], pa);
        pa = fmaf(ca0.z, h1v[2], pa); pa = fmaf(ca0.w, h1v[3], pa);
        pa = fmaf(ca1.x, h1v[4], pa); pa = fmaf(ca1.y, h1v[5], pa);
        pa = fmaf(ca1.z, h1v[6], pa); pa = fmaf(ca1.w, h1v[7], pa);
        pb = fmaf(cb0.x, h1v[0], pb); pb = fmaf(cb0.y, h1v[1], pb);
        pb = fmaf(cb0.z, h1v[2], pb); pb = fmaf(cb0.w, h1v[3], pb);
        pb = fmaf(cb1.x, h1v[4], pb); pb = fmaf(cb1.y, h1v[5], pb);
        pb = fmaf(cb1.z, h1v[6], pb); pb = fmaf(cb1.w, h1v[7], pb);
        atomicAdd(&g_pre[p][g0], pa);
        atomicAdd(&g_pre[p][g0 + 1], pb);
    }
    // d_out init (poisoned each replay): ordered before all projection atomics
    // by the barrier below. o = t*2+k.
    if (blockIdx.x == 0 && tid < 2 * T) out[tid] = out_b[tid & 1];
    grid_barrier();   // the ONLY grid barrier

    // ---- Segment B (fully block-local): dec0 scan for ALL 1024 channels
    //      (2 per thread) -> s_d0, then GEMM + dec1 scan + projection.
    {
        const float pre_a = g_pre[p][g0] + dec_b0[g0];          // coherent
        const float pre_b = g_pre[p][g0 + 1] + dec_b0[g0 + 1];
        const float ua = dec_u0[g0], ub = dec_u0[g0 + 1];
        float da = 0.0f, db = 0.0f;
        float* s_d0 = smem + OFF_D0;
#pragma unroll
        for (int t = 0; t < T; t++) {
            da = fmaxf(fmaf(ua, da, pre_a), 0.0f);
            db = fmaxf(fmaf(ub, db, pre_b), 0.0f);
            s_d0[t * H + g0] = da;
            s_d0[t * H + g0 + 1] = db;
        }
        __syncthreads();

        // GEMM: 16 warps = 4 row-pairs x 2 K-halves x 2 t-halves;
        // 2 rows x 10 t x 512 K per warp. Weights in regs, v from smem (LDS).
        const float4* d0b = (const float4*)s_d0 + th * 10 * (H / 4) + kh * 128;
        float acc0[10], acc1[10];
#pragma unroll
        for (int t = 0; t < 10; t++) { acc0[t] = 0.0f; acc1[t] = 0.0f; }
#pragma unroll
        for (int j = 0; j < 4; j++) {
            const int c = j * 32 + lane;
            const float4 a = w8[j];
            const float4 q = w8[4 + j];
            float4 v[5];
#pragma unroll
            for (int t = 0; t < 5; t++) v[t] = d0b[t * 256 + c];
#pragma unroll
            for (int t = 0; t < 5; t++) {
                acc0[t] = fmaf(a.x, v[t].x, acc0[t]); acc0[t] = fmaf(a.y, v[t].y, acc0[t]);
                acc0[t] = fmaf(a.z, v[t].z, acc0[t]); acc0[t] = fmaf(a.w, v[t].w, acc0[t]);
                acc1[t] = fmaf(q.x, v[t].x, acc1[t]); acc1[t] = fmaf(q.y, v[t].y, acc1[t]);
                acc1[t] = fmaf(q.z, v[t].z, acc1[t]); acc1[t] = fmaf(q.w, v[t].w, acc1[t]);
            }
#pragma unroll
            for (int t = 0; t < 5; t++) v[t] = d0b[(t + 5) * 256 + c];
#pragma unroll
            for (int t = 0; t < 5; t++) {
                acc0[t+5] = fmaf(a.x, v[t].x, acc0[t+5]); acc0[t+5] = fmaf(a.y, v[t].y, acc0[t+5]);
                acc0[t+5] = fmaf(a.z, v[t].z, acc0[t+5]); acc0[t+5] = fmaf(a.w, v[t].w, acc0[t+5]);
                acc1[t+5] = fmaf(q.x, v[t].x, acc1[t+5]); acc1[t+5] = fmaf(q.y, v[t].y, acc1[t+5]);
                acc1[t+5] = fmaf(q.z, v[t].z, acc1[t+5]); acc1[t+5] = fmaf(q.w, v[t].w, acc1[t+5]);
            }
        }
        float* s_pre = smem + OFF_PRE;     // [2][8][T]
#pragma unroll
        for (int t = 0; t < 10; t++) {
            acc0[t] = warp_reduce(acc0[t]);
            acc1[t] = warp_reduce(acc1[t]);
        }
        if (lane == 0) {
#pragma unroll
            for (int t = 0; t < 10; t++)
                s_pre[(kh * 8 + rp * 2) * T + th * 10 + t] = acc0[t];
        }
        if (lane == 1) {
#pragma unroll
            for (int t = 0; t < 10; t++)
                s_pre[(kh * 8 + rp * 2 + 1) * T + th * 10 + t] = acc1[t];
        }
        __syncthreads();

        // dec1 scan -> s_d1 (combine K-half partials), 8 threads.
        float* s_d1 = smem + OFF_D1;       // [8][T]
        if (tid < 8) {
            const int hh = blockIdx.x * 8 + tid;
            const float bb = dec_b1[hh], uu = dec_u1[hh];
            float d = 0.0f;
#pragma unroll
            for (int t = 0; t < T; t++) {
                d = fmaxf(fmaf(uu, d, s_pre[tid * T + t] + s_pre[(8 + tid) * T + t] + bb), 0.0f);
                s_d1[tid * T + t] = d;
            }
        }
        __syncthreads();

        // Projection, block-pre-reduced: one atomicAdd per (t,k) per block.
        if (tid < 2 * T) {
            const int t = tid >> 1, k = tid & 1;
            const float* owr = out_w + (size_t)k * H + blockIdx.x * 8;
            float sum = 0.0f;
#pragma unroll
            for (int ch = 0; ch < 8; ch++)
                sum = fmaf(owr[ch], s_d1[ch * T + t], sum);
            atomicAdd(out + tid, sum);
        }
    }
}

extern "C" void kernel_launch(void* const* d_in, const int* in_sizes, int n_in,
                              void* d_out, int out_size) {
    const float* x      = (const float*)d_in[0];
    const float* enc_w0 = (const float*)d_in[1];
    // d_in[2] = enc_u0: unused (only t=0 encoder state needed, h_{-1}=0)
    const float* enc_b0 = (const float*)d_in[3];
    const float* enc_w1 = (const float*)d_in[4];
    // d_in[5] = enc_u1: unused
    const float* enc_b1 = (const float*)d_in[6];
    const float* dec_w0 = (const float*)d_in[7];
    const float* dec_u0 = (const float*)d_in[8];
    const float* dec_b0 = (const float*)d_in[9];
    const float* dec_w1 = (const float*)d_in[10];
    const float* dec_u1 = (const float*)d_in[11];
    const float* dec_b1 = (const float*)d_in[12];
    const float* out_w  = (const float*)d_in[13];
    const float* out_b  = (const float*)d_in[14];
    float* out = (float*)d_out;

    const int smem_bytes = SMEM_FLOATS * (int)sizeof(float);
    cudaFuncSetAttribute(fused_net, cudaFuncAttributeMaxDynamicSharedMemorySize,
                         smem_bytes);   // idempotent host call; not a graph node

    fused_net<<<GRID, BLK, smem_bytes>>>(x, enc_w0, enc_b0, enc_w1, enc_b1,
                                         dec_w0, dec_u0, dec_b0,
                                         dec_w1, dec_u1, dec_b1,
                                         out_w, out_b, out);
}